// round 12
// baseline (speedup 1.0000x reference)
#include <cuda_runtime.h>
#include <cuda_bf16.h>
#include <cstdint>
#include <math.h>

#define NN 4096
#define FF 512
#define NH 8
#define DH 64
#define NC 40
#define LRA 0.2f

// ---------------- scratch (__device__ globals; no allocs) ----------------
__device__ uint4 g_xf_hi[(NN/16)*32*32];        // x A-frags hi
__device__ uint4 g_xf_lo[(NN/16)*32*32];
__device__ uint4 g_w1f[NH*32*8*32];             // W1 B-frags {bh01,bh89,bl01,bl89}
__device__ uint4 g_whf[NH*256*8*32];            // Wh^T B-frags for att1
__device__ float4 g_t1[NH*NN];                  // {e1p, e1n, f1, 0}
__device__ float4 g_t2[NH*NN];
__device__ unsigned g_adjbit [NN*(NN/32)];      // packed adj[1]
__device__ unsigned g_adjbit2[NN*(NN/32)];      // packed adj[0]
__device__ float g_p1 [2*NN*FF];                // att1 partial acc (per j-half)
__device__ float g_pd1[2*NH*NN];                // att1 partial denom
__device__ __nv_bfloat16 g_W2T_hi[NC*NN];       // Wh2^T hi bf16: [d][n]
__device__ __nv_bfloat16 g_W2T_lo[NC*NN];
__device__ float4 g_t1b[NN], g_t2b[NN];
__device__ float g_p2 [4*NN*NC];                // att2 partial acc
__device__ float g_pd2[4*NN];

// ---------------- helpers ----------------
__device__ __forceinline__ float elu1(float v){ return v > 0.f ? v : expm1f(v); }
__device__ __forceinline__ uint32_t bf2pack(float e0, float e1){
    uint32_t r;
    asm("cvt.rn.bf16x2.f32 %0, %1, %2;" : "=r"(r) : "f"(e1), "f"(e0));
    return r;
}
__device__ __forceinline__ float bflow (uint32_t u){ return __uint_as_float(u << 16); }
__device__ __forceinline__ float bfhigh(uint32_t u){ return __uint_as_float(u & 0xFFFF0000u); }

__device__ __forceinline__ void mma_bf16(float* d, const uint32_t* a, uint32_t b0, uint32_t b1){
    asm volatile("mma.sync.aligned.m16n8k16.row.col.f32.bf16.bf16.f32 "
        "{%0,%1,%2,%3}, {%4,%5,%6,%7}, {%8,%9}, {%0,%1,%2,%3};"
        : "+f"(d[0]), "+f"(d[1]), "+f"(d[2]), "+f"(d[3])
        : "r"(a[0]), "r"(a[1]), "r"(a[2]), "r"(a[3]), "r"(b0), "r"(b1));
}

#define PV(tt, e1p_, e1n_, f1_, w, bit, out) { \
    float s_ = (f1_) + (tt).z; \
    float v_ = (s_ >= 0.f) ? (e1p_)*(tt).x : (e1n_)*(tt).y; \
    out = (((w) >> (bit)) & 1u) ? v_ : 0.f; }

// ================= kernel 0: pack adjacency into bitmasks (both layers) ===========
__global__ void k_pack(const int* __restrict__ adjm){
    int layer = blockIdx.y;
    const int* base = adjm + (layer ? 0 : (size_t)NN*NN);
    unsigned* dstA  = layer ? g_adjbit2 : g_adjbit;
    int w = blockIdx.x*8 + (threadIdx.x>>5);
    int lane = threadIdx.x & 31;
    const int* src = base + (size_t)w*1024;
    unsigned* dst = dstA + (size_t)w*32;
    #pragma unroll 4
    for (int k = 0; k < 32; k++){
        int v = src[k*32 + lane];
        unsigned m = __ballot_sync(0xffffffffu, v > 0);
        if (lane == 0) dst[k] = m;
    }
}

// ====== kernel 0b: split x (A-frags) and W1 (B-frags) into hi/lo bf16 ======
__global__ void k_split(const float* __restrict__ x, const float* __restrict__ W1){
    int idx = blockIdx.x*256 + threadIdx.x;
    if (blockIdx.x < 1024){
        int f = idx >> 5, lane = idx & 31;
        int i16 = f >> 5, c = f & 31;
        int r  = i16*16 + (lane>>2);
        int k0 = c*16 + (lane&3)*2;
        float2 p00 = *(const float2*)(x + (size_t)r*FF + k0);
        float2 p10 = *(const float2*)(x + (size_t)(r+8)*FF + k0);
        float2 p01 = *(const float2*)(x + (size_t)r*FF + k0 + 8);
        float2 p11 = *(const float2*)(x + (size_t)(r+8)*FF + k0 + 8);
        uint32_t a0 = bf2pack(p00.x, p00.y);
        uint32_t a1 = bf2pack(p10.x, p10.y);
        uint32_t a2 = bf2pack(p01.x, p01.y);
        uint32_t a3 = bf2pack(p11.x, p11.y);
        g_xf_hi[idx] = make_uint4(a0, a1, a2, a3);
        uint32_t l0 = bf2pack(p00.x - bflow(a0), p00.y - bfhigh(a0));
        uint32_t l1 = bf2pack(p10.x - bflow(a1), p10.y - bfhigh(a1));
        uint32_t l2 = bf2pack(p01.x - bflow(a2), p01.y - bfhigh(a2));
        uint32_t l3 = bf2pack(p11.x - bflow(a3), p11.y - bfhigh(a3));
        g_xf_lo[idx] = make_uint4(l0, l1, l2, l3);
    } else {
        int id2 = idx - 262144;                  // [0, 65536)
        int f = id2 >> 5, lane = id2 & 31;
        int h = f >> 8, rem = f & 255;
        int c = rem >> 3, nf = rem & 7;
        int k0 = c*16 + (lane&3)*2;
        int n  = nf*8 + (lane>>2);
        const float* Wb = W1 + (size_t)h*FF*DH;
        float w0 = Wb[(size_t)k0*DH + n];
        float w1 = Wb[(size_t)(k0+1)*DH + n];
        float w2 = Wb[(size_t)(k0+8)*DH + n];
        float w3 = Wb[(size_t)(k0+9)*DH + n];
        uint32_t h01 = bf2pack(w0, w1), h89 = bf2pack(w2, w3);
        uint32_t l01 = bf2pack(w0 - bflow(h01), w1 - bfhigh(h01));
        uint32_t l89 = bf2pack(w2 - bflow(h89), w3 - bfhigh(h89));
        g_w1f[id2] = make_uint4(h01, h89, l01, l89);
    }
}

// ====== kernel 1: Wh = x @ W1 via HMMA hi/lo; epilogue: whf frags + f/e tables ======
__global__ void __launch_bounds__(256, 3) k_gemm1h(const float* __restrict__ a1){
    extern __shared__ float Ts[];                // [128][68]
    int tid = threadIdx.x, wid = tid>>5, lane = tid&31;
    int i0 = blockIdx.x*128, h = blockIdx.y;
    int tig = lane & 3;
    int f0 = (i0>>4) + wid;

    float acc[8][4];
    #pragma unroll
    for (int nf = 0; nf < 8; nf++) acc[nf][0]=acc[nf][1]=acc[nf][2]=acc[nf][3]=0.f;

    #pragma unroll 4
    for (int c = 0; c < 32; c++){
        uint4 AH = g_xf_hi[(f0*32 + c)*32 + lane];
        uint4 AL = g_xf_lo[(f0*32 + c)*32 + lane];
        #pragma unroll
        for (int nf = 0; nf < 8; nf++){
            uint4 W = g_w1f[((h*32 + c)*8 + nf)*32 + lane];
            mma_bf16(acc[nf], (const uint32_t*)&AH, W.x, W.y);
            mma_bf16(acc[nf], (const uint32_t*)&AH, W.z, W.w);
            mma_bf16(acc[nf], (const uint32_t*)&AL, W.x, W.y);
        }
    }

    int rA = wid*16 + (lane>>2);
    #pragma unroll
    for (int nf = 0; nf < 8; nf++){
        int c0 = nf*8 + tig*2;
        Ts[rA*68 + c0]     = acc[nf][0]; Ts[rA*68 + c0+1]     = acc[nf][1];
        Ts[(rA+8)*68 + c0] = acc[nf][2]; Ts[(rA+8)*68 + c0+1] = acc[nf][3];
    }
    __syncthreads();
    // epilogue A: att1 B-fragments (hi/lo, transposed)
    #pragma unroll
    for (int e = 0; e < 8; e++){
        int eid = e*256 + tid;
        int fh = eid>>5, ln = eid&31;
        int jc = fh>>3, nf = fh&7;
        int jl = jc*16 + (ln&3)*2;
        int d  = nf*8 + (ln>>2);
        float v0 = Ts[jl*68 + d], v1 = Ts[(jl+1)*68 + d];
        float v2 = Ts[(jl+8)*68 + d], v3 = Ts[(jl+9)*68 + d];
        uint32_t h01 = bf2pack(v0, v1), h89 = bf2pack(v2, v3);
        uint32_t l01 = bf2pack(v0 - bflow(h01), v1 - bfhigh(h01));
        uint32_t l89 = bf2pack(v2 - bflow(h89), v3 - bfhigh(h89));
        g_whf[((h*256 + (i0>>4) + jc)*8 + nf)*32 + ln] = make_uint4(h01, h89, l01, l89);
    }
    // epilogue B: f1/f2 + exp tables (2 threads per row)
    {
        int rr = tid>>1, hf = tid&1;
        const float* as = a1 + h*2*DH + hf*32;
        const float* ad = as + DH;
        float p1 = 0.f, p2 = 0.f;
        #pragma unroll 8
        for (int d = 0; d < 32; d++){
            float v = Ts[rr*68 + hf*32 + d];
            p1 += v*as[d]; p2 += v*ad[d];
        }
        p1 += __shfl_xor_sync(0xffffffffu, p1, 1);
        p2 += __shfl_xor_sync(0xffffffffu, p2, 1);
        if (hf == 0){
            g_t1[h*NN + i0 + rr] = make_float4(expf(p1), expf(LRA*p1), p1, 0.f);
            g_t2[h*NN + i0 + rr] = make_float4(expf(p2), expf(LRA*p2), p2, 0.f);
        }
    }
}

// === kernel 3: layer-1 attention, HMMA hi/lo, no smem, j-split x2 ===
__global__ void __launch_bounds__(256, 2) k_att1h(){
    int tid = threadIdx.x, wid = tid>>5, lane = tid&31;
    int h = blockIdx.x, i0 = blockIdx.y*256, jh = blockIdx.z;
    int tig = lane & 3;
    int rA = wid*32 + (lane>>2);

    float e1p[4], e1n[4], f1v[4], ds[4];
    #pragma unroll
    for (int k = 0; k < 4; k++){
        float4 tv = g_t1[h*NN + i0 + rA + 8*k];
        e1p[k] = tv.x; e1n[k] = tv.y; f1v[k] = tv.z; ds[k] = 0.f;
    }

    float acc[2][8][4];
    #pragma unroll
    for (int fr = 0; fr < 2; fr++)
        #pragma unroll
        for (int nf = 0; nf < 8; nf++)
            acc[fr][nf][0]=acc[fr][nf][1]=acc[fr][nf][2]=acc[fr][nf][3]=0.f;

    #pragma unroll 1
    for (int tl = 0; tl < 16; tl++){
        int j0 = jh*2048 + tl*128;
        #pragma unroll 2
        for (int c = 0; c < 8; c++){
            int p0 = c*16 + tig*2;
            float4 tc0 = g_t2[h*NN + j0 + p0];
            float4 tc1 = g_t2[h*NN + j0 + p0 + 1];
            float4 tc2 = g_t2[h*NN + j0 + p0 + 8];
            float4 tc3 = g_t2[h*NN + j0 + p0 + 9];
            int b0 = tig*2, b1 = b0+1, b2 = b0+8, b3 = b0+9;

            float v[4][4];
            #pragma unroll
            for (int k = 0; k < 4; k++){
                uint32_t wb = g_adjbit[(size_t)(i0+rA+8*k)*128 + (j0>>5) + (c>>1)] >> ((c&1)*16);
                PV(tc0, e1p[k], e1n[k], f1v[k], wb, b0, v[k][0]);
                PV(tc1, e1p[k], e1n[k], f1v[k], wb, b1, v[k][1]);
                PV(tc2, e1p[k], e1n[k], f1v[k], wb, b2, v[k][2]);
                PV(tc3, e1p[k], e1n[k], f1v[k], wb, b3, v[k][3]);
                ds[k] += (v[k][0]+v[k][1]) + (v[k][2]+v[k][3]);
            }

            uint32_t ah0[4], al0[4], ah1[4], al1[4];
            ah0[0] = bf2pack(v[0][0], v[0][1]); ah0[1] = bf2pack(v[1][0], v[1][1]);
            ah0[2] = bf2pack(v[0][2], v[0][3]); ah0[3] = bf2pack(v[1][2], v[1][3]);
            ah1[0] = bf2pack(v[2][0], v[2][1]); ah1[1] = bf2pack(v[3][0], v[3][1]);
            ah1[2] = bf2pack(v[2][2], v[2][3]); ah1[3] = bf2pack(v[3][2], v[3][3]);
            al0[0] = bf2pack(v[0][0]-bflow(ah0[0]), v[0][1]-bfhigh(ah0[0]));
            al0[1] = bf2pack(v[1][0]-bflow(ah0[1]), v[1][1]-bfhigh(ah0[1]));
            al0[2] = bf2pack(v[0][2]-bflow(ah0[2]), v[0][3]-bfhigh(ah0[2]));
            al0[3] = bf2pack(v[1][2]-bflow(ah0[3]), v[1][3]-bfhigh(ah0[3]));
            al1[0] = bf2pack(v[2][0]-bflow(ah1[0]), v[2][1]-bfhigh(ah1[0]));
            al1[1] = bf2pack(v[3][0]-bflow(ah1[1]), v[3][1]-bfhigh(ah1[1]));
            al1[2] = bf2pack(v[2][2]-bflow(ah1[2]), v[2][3]-bfhigh(ah1[2]));
            al1[3] = bf2pack(v[3][2]-bflow(ah1[3]), v[3][3]-bfhigh(ah1[3]));

            int jcg = (j0>>4) + c;
            const uint4* Wp = &g_whf[((h*256 + jcg)*8)*32 + lane];
            #pragma unroll
            for (int nf = 0; nf < 8; nf++){
                uint4 W = Wp[nf*32];
                mma_bf16(acc[0][nf], ah0, W.x, W.y);
                mma_bf16(acc[0][nf], ah0, W.z, W.w);
                mma_bf16(acc[0][nf], al0, W.x, W.y);
                mma_bf16(acc[1][nf], ah1, W.x, W.y);
                mma_bf16(acc[1][nf], ah1, W.z, W.w);
                mma_bf16(acc[1][nf], al1, W.x, W.y);
            }
        }
    }

    #pragma unroll
    for (int k = 0; k < 4; k++){
        ds[k] += __shfl_xor_sync(0xffffffffu, ds[k], 1);
        ds[k] += __shfl_xor_sync(0xffffffffu, ds[k], 2);
    }
    if (tig == 0){
        #pragma unroll
        for (int k = 0; k < 4; k++)
            g_pd1[jh*NH*NN + h*NN + i0 + rA + 8*k] = ds[k];
    }

    float* Pb = g_p1 + (size_t)jh*NN*FF;
    #pragma unroll
    for (int fr = 0; fr < 2; fr++){
        float* base0 = &Pb[(size_t)(i0 + rA + 16*fr)*FF + h*DH + tig*2];
        float* base1 = &Pb[(size_t)(i0 + rA + 16*fr + 8)*FF + h*DH + tig*2];
        #pragma unroll
        for (int nf = 0; nf < 8; nf++){
            *(float2*)(base0 + nf*8) = make_float2(acc[fr][nf][0], acc[fr][nf][1]);
            *(float2*)(base1 + nf*8) = make_float2(acc[fr][nf][2], acc[fr][nf][3]);
        }
    }
}

// ==== kernel 4: fused {red1+ELU} -> gemm2 -> {W2T hi/lo + layer-2 tables} ====
__global__ void k_gemm2f(const float* __restrict__ Wo, const float* __restrict__ ao){
    __shared__ float As[32][65];
    __shared__ float Bs[64][40];
    __shared__ float Tw[40][33];
    __shared__ float invS[8][32];
    int tid = threadIdx.x;
    int row = tid & 31, cg = tid >> 5;
    int i0 = blockIdx.x*32;
    {
        int hh = tid>>5, rr = tid&31;
        float dsum = g_pd1[hh*NN + i0 + rr] + g_pd1[NH*NN + hh*NN + i0 + rr];
        invS[hh][rr] = 1.0f / dsum;
    }
    float acc[5] = {};
    for (int k0 = 0; k0 < FF; k0 += 64){
        __syncthreads();
        int hh = k0>>6;
        #pragma unroll
        for (int t = 0; t < 8; t++){
            int idx = tid + t*256;
            int rr = idx>>6, c = idx&63;
            float a = g_p1[(size_t)(i0+rr)*FF + k0 + c]
                    + g_p1[(size_t)NN*FF + (size_t)(i0+rr)*FF + k0 + c];
            As[rr][c] = elu1(a * invS[hh][rr]);
        }
        for (int idx = tid; idx < 64*NC; idx += 256){
            int rr = idx/NC, c = idx - rr*NC;
            Bs[rr][c] = Wo[(size_t)(k0+rr)*NC + c];
        }
        __syncthreads();
        #pragma unroll 8
        for (int kk = 0; kk < 64; kk++){
            float a = As[row][kk];
            #pragma unroll
            for (int q = 0; q < 5; q++) acc[q] += a * Bs[kk][cg*5+q];
        }
    }
    #pragma unroll
    for (int q = 0; q < 5; q++) Tw[cg*5+q][row] = acc[q];
    __syncthreads();
    for (int e = tid; e < NC*32; e += 256){
        int d = e>>5, il = e&31;
        float v = Tw[d][il];
        __nv_bfloat16 hb = __float2bfloat16(v);
        __nv_bfloat16 lb = __float2bfloat16(v - __bfloat162float(hb));
        g_W2T_hi[(size_t)d*NN + i0 + il] = hb;
        g_W2T_lo[(size_t)d*NN + i0 + il] = lb;
    }
    if (tid < 32){
        float p1 = 0.f, p2 = 0.f;
        #pragma unroll 8
        for (int d = 0; d < NC; d++){
            float v = Tw[d][tid];
            p1 += v*ao[d]; p2 += v*ao[NC+d];
        }
        g_t1b[i0+tid] = make_float4(expf(p1), expf(LRA*p1), p1, 0.f);
        g_t2b[i0+tid] = make_float4(expf(p2), expf(LRA*p2), p2, 0.f);
    }
}

// === kernel 6: layer-2 attention, HMMA hi/lo, j-split x4 ===
__global__ void __launch_bounds__(256) k_att2_mma(){
    __shared__ float4 s_tbl[128];
    __shared__ uint4 s_adj[128];
    __shared__ uint2 Wf_hi[40][32];
    __shared__ uint2 Wf_lo[40][32];

    int tid = threadIdx.x, wid = tid>>5, lane = tid&31;
    int i0 = blockIdx.x*128, js = blockIdx.y;
    int tig = lane & 3;
    int r0l = wid*16 + (lane>>2);
    int r1l = r0l + 8;

    float4 t1a = g_t1b[i0 + r0l];
    float4 t1b = g_t1b[i0 + r1l];
    float e1p0=t1a.x, e1n0=t1a.y, f10=t1a.z;
    float e1p1=t1b.x, e1n1=t1b.y, f11=t1b.z;
    float ds0 = 0.f, ds1 = 0.f;

    float acc[5][4];
    #pragma unroll
    for (int nf = 0; nf < 5; nf++){ acc[nf][0]=acc[nf][1]=acc[nf][2]=acc[nf][3]=0.f; }

    #pragma unroll 1
    for (int t = js*8; t < js*8 + 8; t++){
        int j0 = t*128;
        __syncthreads();
        if (tid < 128){
            s_tbl[tid] = g_t2b[j0 + tid];
            s_adj[tid] = *(const uint4*)(g_adjbit2 + (size_t)(i0+tid)*128 + t*4);
        }
        #pragma unroll
        for (int q = 0; q < 5; q++){
            int e = q*256 + tid;
            int fh = e>>5, ln = e&31;
            int nf = fh>>3, c = fh&7;
            int d = nf*8 + (ln>>2);
            int jj = c*16 + (ln&3)*2;
            size_t src = (size_t)d*NN + j0 + jj;
            Wf_hi[fh][ln] = make_uint2(*(const uint32_t*)(g_W2T_hi + src),
                                       *(const uint32_t*)(g_W2T_hi + src + 8));
            Wf_lo[fh][ln] = make_uint2(*(const uint32_t*)(g_W2T_lo + src),
                                       *(const uint32_t*)(g_W2T_lo + src + 8));
        }
        __syncthreads();

        #pragma unroll 2
        for (int c = 0; c < 8; c++){
            int p0 = c*16 + tig*2;
            float4 ta = s_tbl[p0], tb = s_tbl[p0+1], tc = s_tbl[p0+8], td = s_tbl[p0+9];
            uint32_t w0 = ((const uint32_t*)&s_adj[r0l])[c>>1] >> ((c&1)*16);
            uint32_t w1 = ((const uint32_t*)&s_adj[r1l])[c>>1] >> ((c&1)*16);
            int b0 = tig*2, b1 = b0+1, b2 = b0+8, b3 = b0+9;

            float v00,v01,v02,v03, v10,v11,v12,v13;
            PV(ta,e1p0,e1n0,f10,w0,b0,v00); PV(tb,e1p0,e1n0,f10,w0,b1,v01);
            PV(tc,e1p0,e1n0,f10,w0,b2,v02); PV(td,e1p0,e1n0,f10,w0,b3,v03);
            PV(ta,e1p1,e1n1,f11,w1,b0,v10); PV(tb,e1p1,e1n1,f11,w1,b1,v11);
            PV(tc,e1p1,e1n1,f11,w1,b2,v12); PV(td,e1p1,e1n1,f11,w1,b3,v13);
            ds0 += (v00+v01)+(v02+v03);
            ds1 += (v10+v11)+(v12+v13);

            uint32_t ah[4], al[4];
            ah[0] = bf2pack(v00, v01); ah[1] = bf2pack(v10, v11);
            ah[2] = bf2pack(v02, v03); ah[3] = bf2pack(v12, v13);
            al[0] = bf2pack(v00 - bflow(ah[0]), v01 - bfhigh(ah[0]));
            al[1] = bf2pack(v10 - bflow(ah[1]), v11 - bfhigh(ah[1]));
            al[2] = bf2pack(v02 - bflow(ah[2]), v03 - bfhigh(ah[2]));
            al[3] = bf2pack(v12 - bflow(ah[3]), v13 - bfhigh(ah[3]));

            #pragma unroll
            for (int nf = 0; nf < 5; nf++){
                uint2 bh = Wf_hi[nf*8+c][lane];
                uint2 bl = Wf_lo[nf*8+c][lane];
                mma_bf16(acc[nf], ah, bh.x, bh.y);
                mma_bf16(acc[nf], ah, bl.x, bl.y);
                mma_bf16(acc[nf], al, bh.x, bh.y);
            }
        }
    }

    ds0 += __shfl_xor_sync(0xffffffffu, ds0, 1);
    ds0 += __shfl_xor_sync(0xffffffffu, ds0, 2);
    ds1 += __shfl_xor_sync(0xffffffffu, ds1, 1);
    ds1 += __shfl_xor_sync(0xffffffffu, ds1, 2);
    if (tig == 0){
        g_pd2[js*NN + i0 + r0l] = ds0;
        g_pd2[js*NN + i0 + r1l] = ds1;
    }

    float* Pb = g_p2 + (size_t)js*NN*NC;
    float* base0 = &Pb[(size_t)(i0+r0l)*NC + tig*2];
    float* base1 = &Pb[(size_t)(i0+r1l)*NC + tig*2];
    #pragma unroll
    for (int nf = 0; nf < 5; nf++){
        *(float2*)(base0 + nf*8) = make_float2(acc[nf][0], acc[nf][1]);
        *(float2*)(base1 + nf*8) = make_float2(acc[nf][2], acc[nf][3]);
    }
}

// ====== kernel 7: fused merge + ELU + log_softmax (one warp per row) ======
__global__ void k_final(float* __restrict__ out){
    int w = threadIdx.x>>5, lane = threadIdx.x & 31;
    int i = blockIdx.x*8 + w;
    float dsum = g_pd2[i] + g_pd2[NN+i] + g_pd2[2*NN+i] + g_pd2[3*NN+i];
    float inv = 1.0f / dsum;
    size_t b = (size_t)i*NC;
    float v0 = elu1((g_p2[b+lane] + g_p2[(size_t)NN*NC + b + lane]
                   + g_p2[(size_t)2*NN*NC + b + lane] + g_p2[(size_t)3*NN*NC + b + lane]) * inv);
    float v1 = -1e30f;
    if (lane < 8){
        size_t c = b + 32 + lane;
        v1 = elu1((g_p2[c] + g_p2[(size_t)NN*NC + c]
                 + g_p2[(size_t)2*NN*NC + c] + g_p2[(size_t)3*NN*NC + c]) * inv);
    }
    float m = fmaxf(v0, v1);
    #pragma unroll
    for (int o = 16; o; o >>= 1) m = fmaxf(m, __shfl_xor_sync(0xffffffffu, m, o));
    float s = expf(v0 - m) + ((lane < 8) ? expf(v1 - m) : 0.f);
    #pragma unroll
    for (int o = 16; o; o >>= 1) s += __shfl_xor_sync(0xffffffffu, s, o);
    float ls = m + logf(s);
    out[b + lane] = v0 - ls;
    if (lane < 8) out[b + 32 + lane] = v1 - ls;
}

// ============================== launch ==============================
extern "C" void kernel_launch(void* const* d_in, const int* in_sizes, int n_in,
                              void* d_out, int out_size){
    const float* x  = (const float*)d_in[0];
    const int*   adj= (const int*)  d_in[1];
    const float* W1 = (const float*)d_in[2];
    const float* a1 = (const float*)d_in[3];
    const float* Wo = (const float*)d_in[4];
    const float* ao = (const float*)d_in[5];
    float* out = (float*)d_out;

    static int smem_set = 0;
    if (!smem_set){
        cudaFuncSetAttribute(k_gemm1h, cudaFuncAttributeMaxDynamicSharedMemorySize, 128*68*4);
        smem_set = 1;
    }

    k_pack   <<<dim3(2048, 2), 256>>>(adj);
    k_split  <<<1280, 256>>>(x, W1);
    k_gemm1h <<<dim3(32, 8), 256, 128*68*4>>>(a1);
    k_att1h  <<<dim3(8, 16, 2), 256>>>();
    k_gemm2f <<<128, 256>>>(Wo, ao);
    k_att2_mma<<<dim3(32, 4), 256>>>();
    k_final  <<<512, 256>>>(out);
}

// round 13
// speedup vs baseline: 1.0038x; 1.0038x over previous
#include <cuda_runtime.h>
#include <cuda_bf16.h>
#include <cstdint>
#include <math.h>

#define NN 4096
#define FF 512
#define NH 8
#define DH 64
#define NC 40
#define LRA 0.2f

// ---------------- scratch (__device__ globals; no allocs) ----------------
__device__ uint4 g_xf_hi[(NN/16)*32*32];        // x A-frags hi
__device__ uint4 g_xf_lo[(NN/16)*32*32];
__device__ uint4 g_w1f[NH*32*8*32];             // W1 B-frags {bh01,bh89,bl01,bl89}
__device__ uint4 g_whf[NH*256*8*32];            // Wh^T B-frags for att1
__device__ float4 g_t1[NH*NN];                  // {e1p, e1n, f1, 0}
__device__ float4 g_t2[NH*NN];
__device__ unsigned g_adjbit [NN*(NN/32)];      // packed adj[1]
__device__ unsigned g_adjbit2[NN*(NN/32)];      // packed adj[0]
__device__ float g_p1 [2*NN*FF];                // att1 partial acc (per j-half)
__device__ float g_pd1[2*NH*NN];                // att1 partial denom
__device__ __nv_bfloat16 g_W2T_hi[NC*NN];       // Wh2^T hi bf16: [d][n]
__device__ __nv_bfloat16 g_W2T_lo[NC*NN];
__device__ float4 g_t1b[NN], g_t2b[NN];
__device__ float g_p2 [4*NN*NC];                // att2 partial acc
__device__ float g_pd2[4*NN];

// ---------------- helpers ----------------
__device__ __forceinline__ float elu1(float v){ return v > 0.f ? v : expm1f(v); }
__device__ __forceinline__ uint32_t bf2pack(float e0, float e1){
    uint32_t r;
    asm("cvt.rn.bf16x2.f32 %0, %1, %2;" : "=r"(r) : "f"(e1), "f"(e0));
    return r;
}
__device__ __forceinline__ float bflow (uint32_t u){ return __uint_as_float(u << 16); }
__device__ __forceinline__ float bfhigh(uint32_t u){ return __uint_as_float(u & 0xFFFF0000u); }

__device__ __forceinline__ void mma_bf16(float* d, const uint32_t* a, uint32_t b0, uint32_t b1){
    asm volatile("mma.sync.aligned.m16n8k16.row.col.f32.bf16.bf16.f32 "
        "{%0,%1,%2,%3}, {%4,%5,%6,%7}, {%8,%9}, {%0,%1,%2,%3};"
        : "+f"(d[0]), "+f"(d[1]), "+f"(d[2]), "+f"(d[3])
        : "r"(a[0]), "r"(a[1]), "r"(a[2]), "r"(a[3]), "r"(b0), "r"(b1));
}

#define PV(tt, e1p_, e1n_, f1_, w, bit, out) { \
    float s_ = (f1_) + (tt).z; \
    float v_ = (s_ >= 0.f) ? (e1p_)*(tt).x : (e1n_)*(tt).y; \
    out = (((w) >> (bit)) & 1u) ? v_ : 0.f; }

// ================= kernel 0: pack adjacency into bitmasks (both layers) ===========
__global__ void k_pack(const int* __restrict__ adjm){
    int layer = blockIdx.y;
    const int* base = adjm + (layer ? 0 : (size_t)NN*NN);
    unsigned* dstA  = layer ? g_adjbit2 : g_adjbit;
    int w = blockIdx.x*8 + (threadIdx.x>>5);
    int lane = threadIdx.x & 31;
    const int* src = base + (size_t)w*1024;
    unsigned* dst = dstA + (size_t)w*32;
    #pragma unroll 4
    for (int k = 0; k < 32; k++){
        int v = src[k*32 + lane];
        unsigned m = __ballot_sync(0xffffffffu, v > 0);
        if (lane == 0) dst[k] = m;
    }
}

// ====== kernel 0b: split x (A-frags) and W1 (B-frags) into hi/lo bf16 ======
__global__ void k_split(const float* __restrict__ x, const float* __restrict__ W1){
    int idx = blockIdx.x*256 + threadIdx.x;
    if (blockIdx.x < 1024){
        int f = idx >> 5, lane = idx & 31;
        int i16 = f >> 5, c = f & 31;
        int r  = i16*16 + (lane>>2);
        int k0 = c*16 + (lane&3)*2;
        float2 p00 = *(const float2*)(x + (size_t)r*FF + k0);
        float2 p10 = *(const float2*)(x + (size_t)(r+8)*FF + k0);
        float2 p01 = *(const float2*)(x + (size_t)r*FF + k0 + 8);
        float2 p11 = *(const float2*)(x + (size_t)(r+8)*FF + k0 + 8);
        uint32_t a0 = bf2pack(p00.x, p00.y);
        uint32_t a1 = bf2pack(p10.x, p10.y);
        uint32_t a2 = bf2pack(p01.x, p01.y);
        uint32_t a3 = bf2pack(p11.x, p11.y);
        g_xf_hi[idx] = make_uint4(a0, a1, a2, a3);
        uint32_t l0 = bf2pack(p00.x - bflow(a0), p00.y - bfhigh(a0));
        uint32_t l1 = bf2pack(p10.x - bflow(a1), p10.y - bfhigh(a1));
        uint32_t l2 = bf2pack(p01.x - bflow(a2), p01.y - bfhigh(a2));
        uint32_t l3 = bf2pack(p11.x - bflow(a3), p11.y - bfhigh(a3));
        g_xf_lo[idx] = make_uint4(l0, l1, l2, l3);
    } else {
        int id2 = idx - 262144;                  // [0, 65536)
        int f = id2 >> 5, lane = id2 & 31;
        int h = f >> 8, rem = f & 255;
        int c = rem >> 3, nf = rem & 7;
        int k0 = c*16 + (lane&3)*2;
        int n  = nf*8 + (lane>>2);
        const float* Wb = W1 + (size_t)h*FF*DH;
        float w0 = Wb[(size_t)k0*DH + n];
        float w1 = Wb[(size_t)(k0+1)*DH + n];
        float w2 = Wb[(size_t)(k0+8)*DH + n];
        float w3 = Wb[(size_t)(k0+9)*DH + n];
        uint32_t h01 = bf2pack(w0, w1), h89 = bf2pack(w2, w3);
        uint32_t l01 = bf2pack(w0 - bflow(h01), w1 - bfhigh(h01));
        uint32_t l89 = bf2pack(w2 - bflow(h89), w3 - bfhigh(h89));
        g_w1f[id2] = make_uint4(h01, h89, l01, l89);
    }
}

// ====== kernel 1: Wh = x @ W1 via HMMA hi/lo; epilogue: whf frags + f/e tables ======
__global__ void __launch_bounds__(256, 3) k_gemm1h(const float* __restrict__ a1){
    extern __shared__ float Ts[];                // [128][68]
    int tid = threadIdx.x, wid = tid>>5, lane = tid&31;
    int i0 = blockIdx.x*128, h = blockIdx.y;
    int tig = lane & 3;
    int f0 = (i0>>4) + wid;

    float acc[8][4];
    #pragma unroll
    for (int nf = 0; nf < 8; nf++) acc[nf][0]=acc[nf][1]=acc[nf][2]=acc[nf][3]=0.f;

    #pragma unroll 4
    for (int c = 0; c < 32; c++){
        uint4 AH = g_xf_hi[(f0*32 + c)*32 + lane];
        uint4 AL = g_xf_lo[(f0*32 + c)*32 + lane];
        #pragma unroll
        for (int nf = 0; nf < 8; nf++){
            uint4 W = g_w1f[((h*32 + c)*8 + nf)*32 + lane];
            mma_bf16(acc[nf], (const uint32_t*)&AH, W.x, W.y);
            mma_bf16(acc[nf], (const uint32_t*)&AH, W.z, W.w);
            mma_bf16(acc[nf], (const uint32_t*)&AL, W.x, W.y);
        }
    }

    int rA = wid*16 + (lane>>2);
    #pragma unroll
    for (int nf = 0; nf < 8; nf++){
        int c0 = nf*8 + tig*2;
        Ts[rA*68 + c0]     = acc[nf][0]; Ts[rA*68 + c0+1]     = acc[nf][1];
        Ts[(rA+8)*68 + c0] = acc[nf][2]; Ts[(rA+8)*68 + c0+1] = acc[nf][3];
    }
    __syncthreads();
    // epilogue A: att1 B-fragments (hi/lo, transposed)
    #pragma unroll
    for (int e = 0; e < 8; e++){
        int eid = e*256 + tid;
        int fh = eid>>5, ln = eid&31;
        int jc = fh>>3, nf = fh&7;
        int jl = jc*16 + (ln&3)*2;
        int d  = nf*8 + (ln>>2);
        float v0 = Ts[jl*68 + d], v1 = Ts[(jl+1)*68 + d];
        float v2 = Ts[(jl+8)*68 + d], v3 = Ts[(jl+9)*68 + d];
        uint32_t h01 = bf2pack(v0, v1), h89 = bf2pack(v2, v3);
        uint32_t l01 = bf2pack(v0 - bflow(h01), v1 - bfhigh(h01));
        uint32_t l89 = bf2pack(v2 - bflow(h89), v3 - bfhigh(h89));
        g_whf[((h*256 + (i0>>4) + jc)*8 + nf)*32 + ln] = make_uint4(h01, h89, l01, l89);
    }
    // epilogue B: f1/f2 + exp tables (2 threads per row)
    {
        int rr = tid>>1, hf = tid&1;
        const float* as = a1 + h*2*DH + hf*32;
        const float* ad = as + DH;
        float p1 = 0.f, p2 = 0.f;
        #pragma unroll 8
        for (int d = 0; d < 32; d++){
            float v = Ts[rr*68 + hf*32 + d];
            p1 += v*as[d]; p2 += v*ad[d];
        }
        p1 += __shfl_xor_sync(0xffffffffu, p1, 1);
        p2 += __shfl_xor_sync(0xffffffffu, p2, 1);
        if (hf == 0){
            g_t1[h*NN + i0 + rr] = make_float4(expf(p1), expf(LRA*p1), p1, 0.f);
            g_t2[h*NN + i0 + rr] = make_float4(expf(p2), expf(LRA*p2), p2, 0.f);
        }
    }
}

// === kernel 3: layer-1 attention, HMMA hi/lo, no smem, j-split x2 ===
__global__ void __launch_bounds__(256, 2) k_att1h(){
    int tid = threadIdx.x, wid = tid>>5, lane = tid&31;
    int h = blockIdx.x, i0 = blockIdx.y*256, jh = blockIdx.z;
    int tig = lane & 3;
    int rA = wid*32 + (lane>>2);

    float e1p[4], e1n[4], f1v[4], ds[4];
    #pragma unroll
    for (int k = 0; k < 4; k++){
        float4 tv = g_t1[h*NN + i0 + rA + 8*k];
        e1p[k] = tv.x; e1n[k] = tv.y; f1v[k] = tv.z; ds[k] = 0.f;
    }

    float acc[2][8][4];
    #pragma unroll
    for (int fr = 0; fr < 2; fr++)
        #pragma unroll
        for (int nf = 0; nf < 8; nf++)
            acc[fr][nf][0]=acc[fr][nf][1]=acc[fr][nf][2]=acc[fr][nf][3]=0.f;

    #pragma unroll 1
    for (int tl = 0; tl < 16; tl++){
        int j0 = jh*2048 + tl*128;
        #pragma unroll 2
        for (int c = 0; c < 8; c++){
            int p0 = c*16 + tig*2;
            float4 tc0 = g_t2[h*NN + j0 + p0];
            float4 tc1 = g_t2[h*NN + j0 + p0 + 1];
            float4 tc2 = g_t2[h*NN + j0 + p0 + 8];
            float4 tc3 = g_t2[h*NN + j0 + p0 + 9];
            int b0 = tig*2, b1 = b0+1, b2 = b0+8, b3 = b0+9;

            float v[4][4];
            #pragma unroll
            for (int k = 0; k < 4; k++){
                uint32_t wb = g_adjbit[(size_t)(i0+rA+8*k)*128 + (j0>>5) + (c>>1)] >> ((c&1)*16);
                PV(tc0, e1p[k], e1n[k], f1v[k], wb, b0, v[k][0]);
                PV(tc1, e1p[k], e1n[k], f1v[k], wb, b1, v[k][1]);
                PV(tc2, e1p[k], e1n[k], f1v[k], wb, b2, v[k][2]);
                PV(tc3, e1p[k], e1n[k], f1v[k], wb, b3, v[k][3]);
                ds[k] += (v[k][0]+v[k][1]) + (v[k][2]+v[k][3]);
            }

            uint32_t ah0[4], al0[4], ah1[4], al1[4];
            ah0[0] = bf2pack(v[0][0], v[0][1]); ah0[1] = bf2pack(v[1][0], v[1][1]);
            ah0[2] = bf2pack(v[0][2], v[0][3]); ah0[3] = bf2pack(v[1][2], v[1][3]);
            ah1[0] = bf2pack(v[2][0], v[2][1]); ah1[1] = bf2pack(v[3][0], v[3][1]);
            ah1[2] = bf2pack(v[2][2], v[2][3]); ah1[3] = bf2pack(v[3][2], v[3][3]);
            al0[0] = bf2pack(v[0][0]-bflow(ah0[0]), v[0][1]-bfhigh(ah0[0]));
            al0[1] = bf2pack(v[1][0]-bflow(ah0[1]), v[1][1]-bfhigh(ah0[1]));
            al0[2] = bf2pack(v[0][2]-bflow(ah0[2]), v[0][3]-bfhigh(ah0[2]));
            al0[3] = bf2pack(v[1][2]-bflow(ah0[3]), v[1][3]-bfhigh(ah0[3]));
            al1[0] = bf2pack(v[2][0]-bflow(ah1[0]), v[2][1]-bfhigh(ah1[0]));
            al1[1] = bf2pack(v[3][0]-bflow(ah1[1]), v[3][1]-bfhigh(ah1[1]));
            al1[2] = bf2pack(v[2][2]-bflow(ah1[2]), v[2][3]-bfhigh(ah1[2]));
            al1[3] = bf2pack(v[3][2]-bflow(ah1[3]), v[3][3]-bfhigh(ah1[3]));

            int jcg = (j0>>4) + c;
            const uint4* Wp = &g_whf[((h*256 + jcg)*8)*32 + lane];
            #pragma unroll
            for (int nf = 0; nf < 8; nf++){
                uint4 W = Wp[nf*32];
                mma_bf16(acc[0][nf], ah0, W.x, W.y);
                mma_bf16(acc[0][nf], ah0, W.z, W.w);
                mma_bf16(acc[0][nf], al0, W.x, W.y);
                mma_bf16(acc[1][nf], ah1, W.x, W.y);
                mma_bf16(acc[1][nf], ah1, W.z, W.w);
                mma_bf16(acc[1][nf], al1, W.x, W.y);
            }
        }
    }

    #pragma unroll
    for (int k = 0; k < 4; k++){
        ds[k] += __shfl_xor_sync(0xffffffffu, ds[k], 1);
        ds[k] += __shfl_xor_sync(0xffffffffu, ds[k], 2);
    }
    if (tig == 0){
        #pragma unroll
        for (int k = 0; k < 4; k++)
            g_pd1[jh*NH*NN + h*NN + i0 + rA + 8*k] = ds[k];
    }

    float* Pb = g_p1 + (size_t)jh*NN*FF;
    #pragma unroll
    for (int fr = 0; fr < 2; fr++){
        float* base0 = &Pb[(size_t)(i0 + rA + 16*fr)*FF + h*DH + tig*2];
        float* base1 = &Pb[(size_t)(i0 + rA + 16*fr + 8)*FF + h*DH + tig*2];
        #pragma unroll
        for (int nf = 0; nf < 8; nf++){
            *(float2*)(base0 + nf*8) = make_float2(acc[fr][nf][0], acc[fr][nf][1]);
            *(float2*)(base1 + nf*8) = make_float2(acc[fr][nf][2], acc[fr][nf][3]);
        }
    }
}

// ==== kernel 4: fused {red1+ELU} -> gemm2 -> {W2T hi/lo + layer-2 tables} ====
__global__ void k_gemm2f(const float* __restrict__ Wo, const float* __restrict__ ao){
    __shared__ float As[32][65];
    __shared__ float Bs[64][40];
    __shared__ float Tw[40][33];
    __shared__ float invS[8][32];
    int tid = threadIdx.x;
    int row = tid & 31, cg = tid >> 5;
    int i0 = blockIdx.x*32;
    {
        int hh = tid>>5, rr = tid&31;
        float dsum = g_pd1[hh*NN + i0 + rr] + g_pd1[NH*NN + hh*NN + i0 + rr];
        invS[hh][rr] = 1.0f / dsum;
    }
    float acc[5] = {};
    for (int k0 = 0; k0 < FF; k0 += 64){
        __syncthreads();
        int hh = k0>>6;
        #pragma unroll
        for (int t = 0; t < 8; t++){
            int idx = tid + t*256;
            int rr = idx>>6, c = idx&63;
            float a = g_p1[(size_t)(i0+rr)*FF + k0 + c]
                    + g_p1[(size_t)NN*FF + (size_t)(i0+rr)*FF + k0 + c];
            As[rr][c] = elu1(a * invS[hh][rr]);
        }
        for (int idx = tid; idx < 64*NC; idx += 256){
            int rr = idx/NC, c = idx - rr*NC;
            Bs[rr][c] = Wo[(size_t)(k0+rr)*NC + c];
        }
        __syncthreads();
        #pragma unroll 8
        for (int kk = 0; kk < 64; kk++){
            float a = As[row][kk];
            #pragma unroll
            for (int q = 0; q < 5; q++) acc[q] += a * Bs[kk][cg*5+q];
        }
    }
    #pragma unroll
    for (int q = 0; q < 5; q++) Tw[cg*5+q][row] = acc[q];
    __syncthreads();
    for (int e = tid; e < NC*32; e += 256){
        int d = e>>5, il = e&31;
        float v = Tw[d][il];
        __nv_bfloat16 hb = __float2bfloat16(v);
        __nv_bfloat16 lb = __float2bfloat16(v - __bfloat162float(hb));
        g_W2T_hi[(size_t)d*NN + i0 + il] = hb;
        g_W2T_lo[(size_t)d*NN + i0 + il] = lb;
    }
    if (tid < 32){
        float p1 = 0.f, p2 = 0.f;
        #pragma unroll 8
        for (int d = 0; d < NC; d++){
            float v = Tw[d][tid];
            p1 += v*ao[d]; p2 += v*ao[NC+d];
        }
        g_t1b[i0+tid] = make_float4(expf(p1), expf(LRA*p1), p1, 0.f);
        g_t2b[i0+tid] = make_float4(expf(p2), expf(LRA*p2), p2, 0.f);
    }
}

// === kernel 6: layer-2 attention, HMMA hi/lo, j-split x4 ===
__global__ void __launch_bounds__(256) k_att2_mma(){
    __shared__ float4 s_tbl[128];
    __shared__ uint4 s_adj[128];
    __shared__ uint2 Wf_hi[40][32];
    __shared__ uint2 Wf_lo[40][32];

    int tid = threadIdx.x, wid = tid>>5, lane = tid&31;
    int i0 = blockIdx.x*128, js = blockIdx.y;
    int tig = lane & 3;
    int r0l = wid*16 + (lane>>2);
    int r1l = r0l + 8;

    float4 t1a = g_t1b[i0 + r0l];
    float4 t1b = g_t1b[i0 + r1l];
    float e1p0=t1a.x, e1n0=t1a.y, f10=t1a.z;
    float e1p1=t1b.x, e1n1=t1b.y, f11=t1b.z;
    float ds0 = 0.f, ds1 = 0.f;

    float acc[5][4];
    #pragma unroll
    for (int nf = 0; nf < 5; nf++){ acc[nf][0]=acc[nf][1]=acc[nf][2]=acc[nf][3]=0.f; }

    #pragma unroll 1
    for (int t = js*8; t < js*8 + 8; t++){
        int j0 = t*128;
        __syncthreads();
        if (tid < 128){
            s_tbl[tid] = g_t2b[j0 + tid];
            s_adj[tid] = *(const uint4*)(g_adjbit2 + (size_t)(i0+tid)*128 + t*4);
        }
        #pragma unroll
        for (int q = 0; q < 5; q++){
            int e = q*256 + tid;
            int fh = e>>5, ln = e&31;
            int nf = fh>>3, c = fh&7;
            int d = nf*8 + (ln>>2);
            int jj = c*16 + (ln&3)*2;
            size_t src = (size_t)d*NN + j0 + jj;
            Wf_hi[fh][ln] = make_uint2(*(const uint32_t*)(g_W2T_hi + src),
                                       *(const uint32_t*)(g_W2T_hi + src + 8));
            Wf_lo[fh][ln] = make_uint2(*(const uint32_t*)(g_W2T_lo + src),
                                       *(const uint32_t*)(g_W2T_lo + src + 8));
        }
        __syncthreads();

        #pragma unroll 2
        for (int c = 0; c < 8; c++){
            int p0 = c*16 + tig*2;
            float4 ta = s_tbl[p0], tb = s_tbl[p0+1], tc = s_tbl[p0+8], td = s_tbl[p0+9];
            uint32_t w0 = ((const uint32_t*)&s_adj[r0l])[c>>1] >> ((c&1)*16);
            uint32_t w1 = ((const uint32_t*)&s_adj[r1l])[c>>1] >> ((c&1)*16);
            int b0 = tig*2, b1 = b0+1, b2 = b0+8, b3 = b0+9;

            float v00,v01,v02,v03, v10,v11,v12,v13;
            PV(ta,e1p0,e1n0,f10,w0,b0,v00); PV(tb,e1p0,e1n0,f10,w0,b1,v01);
            PV(tc,e1p0,e1n0,f10,w0,b2,v02); PV(td,e1p0,e1n0,f10,w0,b3,v03);
            PV(ta,e1p1,e1n1,f11,w1,b0,v10); PV(tb,e1p1,e1n1,f11,w1,b1,v11);
            PV(tc,e1p1,e1n1,f11,w1,b2,v12); PV(td,e1p1,e1n1,f11,w1,b3,v13);
            ds0 += (v00+v01)+(v02+v03);
            ds1 += (v10+v11)+(v12+v13);

            uint32_t ah[4], al[4];
            ah[0] = bf2pack(v00, v01); ah[1] = bf2pack(v10, v11);
            ah[2] = bf2pack(v02, v03); ah[3] = bf2pack(v12, v13);
            al[0] = bf2pack(v00 - bflow(ah[0]), v01 - bfhigh(ah[0]));
            al[1] = bf2pack(v10 - bflow(ah[1]), v11 - bfhigh(ah[1]));
            al[2] = bf2pack(v02 - bflow(ah[2]), v03 - bfhigh(ah[2]));
            al[3] = bf2pack(v12 - bflow(ah[3]), v13 - bfhigh(ah[3]));

            #pragma unroll
            for (int nf = 0; nf < 5; nf++){
                uint2 bh = Wf_hi[nf*8+c][lane];
                uint2 bl = Wf_lo[nf*8+c][lane];
                mma_bf16(acc[nf], ah, bh.x, bh.y);
                mma_bf16(acc[nf], ah, bl.x, bl.y);
                mma_bf16(acc[nf], al, bh.x, bh.y);
            }
        }
    }

    ds0 += __shfl_xor_sync(0xffffffffu, ds0, 1);
    ds0 += __shfl_xor_sync(0xffffffffu, ds0, 2);
    ds1 += __shfl_xor_sync(0xffffffffu, ds1, 1);
    ds1 += __shfl_xor_sync(0xffffffffu, ds1, 2);
    if (tig == 0){
        g_pd2[js*NN + i0 + r0l] = ds0;
        g_pd2[js*NN + i0 + r1l] = ds1;
    }

    float* Pb = g_p2 + (size_t)js*NN*NC;
    float* base0 = &Pb[(size_t)(i0+r0l)*NC + tig*2];
    float* base1 = &Pb[(size_t)(i0+r1l)*NC + tig*2];
    #pragma unroll
    for (int nf = 0; nf < 5; nf++){
        *(float2*)(base0 + nf*8) = make_float2(acc[nf][0], acc[nf][1]);
        *(float2*)(base1 + nf*8) = make_float2(acc[nf][2], acc[nf][3]);
    }
}

// ====== kernel 7: fused merge + ELU + log_softmax (one warp per row) ======
__global__ void k_final(float* __restrict__ out){
    int w = threadIdx.x>>5, lane = threadIdx.x & 31;
    int i = blockIdx.x*8 + w;
    float dsum = g_pd2[i] + g_pd2[NN+i] + g_pd2[2*NN+i] + g_pd2[3*NN+i];
    float inv = 1.0f / dsum;
    size_t b = (size_t)i*NC;
    float v0 = elu1((g_p2[b+lane] + g_p2[(size_t)NN*NC + b + lane]
                   + g_p2[(size_t)2*NN*NC + b + lane] + g_p2[(size_t)3*NN*NC + b + lane]) * inv);
    float v1 = -1e30f;
    if (lane < 8){
        size_t c = b + 32 + lane;
        v1 = elu1((g_p2[c] + g_p2[(size_t)NN*NC + c]
                 + g_p2[(size_t)2*NN*NC + c] + g_p2[(size_t)3*NN*NC + c]) * inv);
    }
    float m = fmaxf(v0, v1);
    #pragma unroll
    for (int o = 16; o; o >>= 1) m = fmaxf(m, __shfl_xor_sync(0xffffffffu, m, o));
    float s = expf(v0 - m) + ((lane < 8) ? expf(v1 - m) : 0.f);
    #pragma unroll
    for (int o = 16; o; o >>= 1) s += __shfl_xor_sync(0xffffffffu, s, o);
    float ls = m + logf(s);
    out[b + lane] = v0 - ls;
    if (lane < 8) out[b + 32 + lane] = v1 - ls;
}

// ============================== launch ==============================
extern "C" void kernel_launch(void* const* d_in, const int* in_sizes, int n_in,
                              void* d_out, int out_size){
    const float* x  = (const float*)d_in[0];
    const int*   adj= (const int*)  d_in[1];
    const float* W1 = (const float*)d_in[2];
    const float* a1 = (const float*)d_in[3];
    const float* Wo = (const float*)d_in[4];
    const float* ao = (const float*)d_in[5];
    float* out = (float*)d_out;

    static int smem_set = 0;
    if (!smem_set){
        cudaFuncSetAttribute(k_gemm1h, cudaFuncAttributeMaxDynamicSharedMemorySize, 128*68*4);
        smem_set = 1;
    }

    k_pack   <<<dim3(2048, 2), 256>>>(adj);
    k_split  <<<1280, 256>>>(x, W1);
    k_gemm1h <<<dim3(32, 8), 256, 128*68*4>>>(a1);
    k_att1h  <<<dim3(8, 16, 2), 256>>>();
    k_gemm2f <<<128, 256>>>(Wo, ao);
    k_att2_mma<<<dim3(32, 4), 256>>>();
    k_final  <<<512, 256>>>(out);
}

// round 14
// speedup vs baseline: 1.0041x; 1.0003x over previous
#include <cuda_runtime.h>
#include <cuda_bf16.h>
#include <cstdint>
#include <math.h>

#define NN 4096
#define FF 512
#define NH 8
#define DH 64
#define NC 40
#define LRA 0.2f

// ---------------- scratch (__device__ globals; no allocs) ----------------
__device__ uint4 g_xf_hi[(NN/16)*32*32];        // x A-frags hi
__device__ uint4 g_xf_lo[(NN/16)*32*32];
__device__ uint4 g_w1f[NH*32*8*32];             // W1 B-frags {bh01,bh89,bl01,bl89}
__device__ uint4 g_whf[NH*256*8*32];            // Wh^T B-frags for att1
__device__ float4 g_t1[NH*NN];                  // {e1p, e1n, f1, 0}
__device__ float4 g_t2[NH*NN];
__device__ unsigned g_adjbit [NN*(NN/32)];      // packed adj[1]
__device__ unsigned g_adjbit2[NN*(NN/32)];      // packed adj[0]
__device__ float g_p1 [2*NN*FF];                // att1 partial acc (per j-half)
__device__ float g_pd1[2*NH*NN];                // att1 partial denom
__device__ __nv_bfloat16 g_W2T_hi[NC*NN];       // Wh2^T hi bf16: [d][n]
__device__ __nv_bfloat16 g_W2T_lo[NC*NN];
__device__ float4 g_t1b[NN], g_t2b[NN];
__device__ float g_p2 [4*NN*NC];                // att2 partial acc
__device__ float g_pd2[4*NN];

// ---------------- helpers ----------------
__device__ __forceinline__ float elu1(float v){ return v > 0.f ? v : expm1f(v); }
__device__ __forceinline__ uint32_t bf2pack(float e0, float e1){
    uint32_t r;
    asm("cvt.rn.bf16x2.f32 %0, %1, %2;" : "=r"(r) : "f"(e1), "f"(e0));
    return r;
}
__device__ __forceinline__ float bflow (uint32_t u){ return __uint_as_float(u << 16); }
__device__ __forceinline__ float bfhigh(uint32_t u){ return __uint_as_float(u & 0xFFFF0000u); }

__device__ __forceinline__ void mma_bf16(float* d, const uint32_t* a, uint32_t b0, uint32_t b1){
    asm volatile("mma.sync.aligned.m16n8k16.row.col.f32.bf16.bf16.f32 "
        "{%0,%1,%2,%3}, {%4,%5,%6,%7}, {%8,%9}, {%0,%1,%2,%3};"
        : "+f"(d[0]), "+f"(d[1]), "+f"(d[2]), "+f"(d[3])
        : "r"(a[0]), "r"(a[1]), "r"(a[2]), "r"(a[3]), "r"(b0), "r"(b1));
}

#define PV(tt, e1p_, e1n_, f1_, w, bit, out) { \
    float s_ = (f1_) + (tt).z; \
    float v_ = (s_ >= 0.f) ? (e1p_)*(tt).x : (e1n_)*(tt).y; \
    out = (((w) >> (bit)) & 1u) ? v_ : 0.f; }

// ================= kernel 0: pack adjacency into bitmasks (both layers) ===========
__global__ void k_pack(const int* __restrict__ adjm){
    int layer = blockIdx.y;
    const int* base = adjm + (layer ? 0 : (size_t)NN*NN);
    unsigned* dstA  = layer ? g_adjbit2 : g_adjbit;
    int w = blockIdx.x*8 + (threadIdx.x>>5);
    int lane = threadIdx.x & 31;
    const int* src = base + (size_t)w*1024;
    unsigned* dst = dstA + (size_t)w*32;
    #pragma unroll 4
    for (int k = 0; k < 32; k++){
        int v = src[k*32 + lane];
        unsigned m = __ballot_sync(0xffffffffu, v > 0);
        if (lane == 0) dst[k] = m;
    }
}

// ====== kernel 0b: split x (A-frags) and W1 (B-frags) into hi/lo bf16 ======
__global__ void k_split(const float* __restrict__ x, const float* __restrict__ W1){
    int idx = blockIdx.x*256 + threadIdx.x;
    if (blockIdx.x < 1024){
        int f = idx >> 5, lane = idx & 31;
        int i16 = f >> 5, c = f & 31;
        int r  = i16*16 + (lane>>2);
        int k0 = c*16 + (lane&3)*2;
        float2 p00 = *(const float2*)(x + (size_t)r*FF + k0);
        float2 p10 = *(const float2*)(x + (size_t)(r+8)*FF + k0);
        float2 p01 = *(const float2*)(x + (size_t)r*FF + k0 + 8);
        float2 p11 = *(const float2*)(x + (size_t)(r+8)*FF + k0 + 8);
        uint32_t a0 = bf2pack(p00.x, p00.y);
        uint32_t a1 = bf2pack(p10.x, p10.y);
        uint32_t a2 = bf2pack(p01.x, p01.y);
        uint32_t a3 = bf2pack(p11.x, p11.y);
        g_xf_hi[idx] = make_uint4(a0, a1, a2, a3);
        uint32_t l0 = bf2pack(p00.x - bflow(a0), p00.y - bfhigh(a0));
        uint32_t l1 = bf2pack(p10.x - bflow(a1), p10.y - bfhigh(a1));
        uint32_t l2 = bf2pack(p01.x - bflow(a2), p01.y - bfhigh(a2));
        uint32_t l3 = bf2pack(p11.x - bflow(a3), p11.y - bfhigh(a3));
        g_xf_lo[idx] = make_uint4(l0, l1, l2, l3);
    } else {
        int id2 = idx - 262144;                  // [0, 65536)
        int f = id2 >> 5, lane = id2 & 31;
        int h = f >> 8, rem = f & 255;
        int c = rem >> 3, nf = rem & 7;
        int k0 = c*16 + (lane&3)*2;
        int n  = nf*8 + (lane>>2);
        const float* Wb = W1 + (size_t)h*FF*DH;
        float w0 = Wb[(size_t)k0*DH + n];
        float w1 = Wb[(size_t)(k0+1)*DH + n];
        float w2 = Wb[(size_t)(k0+8)*DH + n];
        float w3 = Wb[(size_t)(k0+9)*DH + n];
        uint32_t h01 = bf2pack(w0, w1), h89 = bf2pack(w2, w3);
        uint32_t l01 = bf2pack(w0 - bflow(h01), w1 - bfhigh(h01));
        uint32_t l89 = bf2pack(w2 - bflow(h89), w3 - bfhigh(h89));
        g_w1f[id2] = make_uint4(h01, h89, l01, l89);
    }
}

// ====== kernel 1: Wh = x @ W1 via HMMA hi/lo; epilogue: whf frags + f/e tables ======
__global__ void __launch_bounds__(256, 3) k_gemm1h(const float* __restrict__ a1){
    extern __shared__ float Ts[];                // [128][68]
    int tid = threadIdx.x, wid = tid>>5, lane = tid&31;
    int i0 = blockIdx.x*128, h = blockIdx.y;
    int tig = lane & 3;
    int f0 = (i0>>4) + wid;

    float acc[8][4];
    #pragma unroll
    for (int nf = 0; nf < 8; nf++) acc[nf][0]=acc[nf][1]=acc[nf][2]=acc[nf][3]=0.f;

    #pragma unroll 4
    for (int c = 0; c < 32; c++){
        uint4 AH = g_xf_hi[(f0*32 + c)*32 + lane];
        uint4 AL = g_xf_lo[(f0*32 + c)*32 + lane];
        #pragma unroll
        for (int nf = 0; nf < 8; nf++){
            uint4 W = g_w1f[((h*32 + c)*8 + nf)*32 + lane];
            mma_bf16(acc[nf], (const uint32_t*)&AH, W.x, W.y);
            mma_bf16(acc[nf], (const uint32_t*)&AH, W.z, W.w);
            mma_bf16(acc[nf], (const uint32_t*)&AL, W.x, W.y);
        }
    }

    int rA = wid*16 + (lane>>2);
    #pragma unroll
    for (int nf = 0; nf < 8; nf++){
        int c0 = nf*8 + tig*2;
        Ts[rA*68 + c0]     = acc[nf][0]; Ts[rA*68 + c0+1]     = acc[nf][1];
        Ts[(rA+8)*68 + c0] = acc[nf][2]; Ts[(rA+8)*68 + c0+1] = acc[nf][3];
    }
    __syncthreads();
    // epilogue A: att1 B-fragments (hi/lo, transposed)
    #pragma unroll
    for (int e = 0; e < 8; e++){
        int eid = e*256 + tid;
        int fh = eid>>5, ln = eid&31;
        int jc = fh>>3, nf = fh&7;
        int jl = jc*16 + (ln&3)*2;
        int d  = nf*8 + (ln>>2);
        float v0 = Ts[jl*68 + d], v1 = Ts[(jl+1)*68 + d];
        float v2 = Ts[(jl+8)*68 + d], v3 = Ts[(jl+9)*68 + d];
        uint32_t h01 = bf2pack(v0, v1), h89 = bf2pack(v2, v3);
        uint32_t l01 = bf2pack(v0 - bflow(h01), v1 - bfhigh(h01));
        uint32_t l89 = bf2pack(v2 - bflow(h89), v3 - bfhigh(h89));
        g_whf[((h*256 + (i0>>4) + jc)*8 + nf)*32 + ln] = make_uint4(h01, h89, l01, l89);
    }
    // epilogue B: f1/f2 + exp tables (2 threads per row)
    {
        int rr = tid>>1, hf = tid&1;
        const float* as = a1 + h*2*DH + hf*32;
        const float* ad = as + DH;
        float p1 = 0.f, p2 = 0.f;
        #pragma unroll 8
        for (int d = 0; d < 32; d++){
            float v = Ts[rr*68 + hf*32 + d];
            p1 += v*as[d]; p2 += v*ad[d];
        }
        p1 += __shfl_xor_sync(0xffffffffu, p1, 1);
        p2 += __shfl_xor_sync(0xffffffffu, p2, 1);
        if (hf == 0){
            g_t1[h*NN + i0 + rr] = make_float4(expf(p1), expf(LRA*p1), p1, 0.f);
            g_t2[h*NN + i0 + rr] = make_float4(expf(p2), expf(LRA*p2), p2, 0.f);
        }
    }
}

// === kernel 3: layer-1 attention, HMMA hi/lo, no smem, j-split x2 ===
__global__ void __launch_bounds__(256, 2) k_att1h(){
    int tid = threadIdx.x, wid = tid>>5, lane = tid&31;
    int h = blockIdx.x, i0 = blockIdx.y*256, jh = blockIdx.z;
    int tig = lane & 3;
    int rA = wid*32 + (lane>>2);

    float e1p[4], e1n[4], f1v[4], ds[4];
    #pragma unroll
    for (int k = 0; k < 4; k++){
        float4 tv = g_t1[h*NN + i0 + rA + 8*k];
        e1p[k] = tv.x; e1n[k] = tv.y; f1v[k] = tv.z; ds[k] = 0.f;
    }

    float acc[2][8][4];
    #pragma unroll
    for (int fr = 0; fr < 2; fr++)
        #pragma unroll
        for (int nf = 0; nf < 8; nf++)
            acc[fr][nf][0]=acc[fr][nf][1]=acc[fr][nf][2]=acc[fr][nf][3]=0.f;

    #pragma unroll 1
    for (int tl = 0; tl < 16; tl++){
        int j0 = jh*2048 + tl*128;
        #pragma unroll 2
        for (int c = 0; c < 8; c++){
            int p0 = c*16 + tig*2;
            float4 tc0 = g_t2[h*NN + j0 + p0];
            float4 tc1 = g_t2[h*NN + j0 + p0 + 1];
            float4 tc2 = g_t2[h*NN + j0 + p0 + 8];
            float4 tc3 = g_t2[h*NN + j0 + p0 + 9];
            int b0 = tig*2, b1 = b0+1, b2 = b0+8, b3 = b0+9;

            float v[4][4];
            #pragma unroll
            for (int k = 0; k < 4; k++){
                uint32_t wb = g_adjbit[(size_t)(i0+rA+8*k)*128 + (j0>>5) + (c>>1)] >> ((c&1)*16);
                PV(tc0, e1p[k], e1n[k], f1v[k], wb, b0, v[k][0]);
                PV(tc1, e1p[k], e1n[k], f1v[k], wb, b1, v[k][1]);
                PV(tc2, e1p[k], e1n[k], f1v[k], wb, b2, v[k][2]);
                PV(tc3, e1p[k], e1n[k], f1v[k], wb, b3, v[k][3]);
                ds[k] += (v[k][0]+v[k][1]) + (v[k][2]+v[k][3]);
            }

            uint32_t ah0[4], al0[4], ah1[4], al1[4];
            ah0[0] = bf2pack(v[0][0], v[0][1]); ah0[1] = bf2pack(v[1][0], v[1][1]);
            ah0[2] = bf2pack(v[0][2], v[0][3]); ah0[3] = bf2pack(v[1][2], v[1][3]);
            ah1[0] = bf2pack(v[2][0], v[2][1]); ah1[1] = bf2pack(v[3][0], v[3][1]);
            ah1[2] = bf2pack(v[2][2], v[2][3]); ah1[3] = bf2pack(v[3][2], v[3][3]);
            al0[0] = bf2pack(v[0][0]-bflow(ah0[0]), v[0][1]-bfhigh(ah0[0]));
            al0[1] = bf2pack(v[1][0]-bflow(ah0[1]), v[1][1]-bfhigh(ah0[1]));
            al0[2] = bf2pack(v[0][2]-bflow(ah0[2]), v[0][3]-bfhigh(ah0[2]));
            al0[3] = bf2pack(v[1][2]-bflow(ah0[3]), v[1][3]-bfhigh(ah0[3]));
            al1[0] = bf2pack(v[2][0]-bflow(ah1[0]), v[2][1]-bfhigh(ah1[0]));
            al1[1] = bf2pack(v[3][0]-bflow(ah1[1]), v[3][1]-bfhigh(ah1[1]));
            al1[2] = bf2pack(v[2][2]-bflow(ah1[2]), v[2][3]-bfhigh(ah1[2]));
            al1[3] = bf2pack(v[3][2]-bflow(ah1[3]), v[3][3]-bfhigh(ah1[3]));

            int jcg = (j0>>4) + c;
            const uint4* Wp = &g_whf[((h*256 + jcg)*8)*32 + lane];
            #pragma unroll
            for (int nf = 0; nf < 8; nf++){
                uint4 W = Wp[nf*32];
                mma_bf16(acc[0][nf], ah0, W.x, W.y);
                mma_bf16(acc[0][nf], ah0, W.z, W.w);
                mma_bf16(acc[0][nf], al0, W.x, W.y);
                mma_bf16(acc[1][nf], ah1, W.x, W.y);
                mma_bf16(acc[1][nf], ah1, W.z, W.w);
                mma_bf16(acc[1][nf], al1, W.x, W.y);
            }
        }
    }

    #pragma unroll
    for (int k = 0; k < 4; k++){
        ds[k] += __shfl_xor_sync(0xffffffffu, ds[k], 1);
        ds[k] += __shfl_xor_sync(0xffffffffu, ds[k], 2);
    }
    if (tig == 0){
        #pragma unroll
        for (int k = 0; k < 4; k++)
            g_pd1[jh*NH*NN + h*NN + i0 + rA + 8*k] = ds[k];
    }

    float* Pb = g_p1 + (size_t)jh*NN*FF;
    #pragma unroll
    for (int fr = 0; fr < 2; fr++){
        float* base0 = &Pb[(size_t)(i0 + rA + 16*fr)*FF + h*DH + tig*2];
        float* base1 = &Pb[(size_t)(i0 + rA + 16*fr + 8)*FF + h*DH + tig*2];
        #pragma unroll
        for (int nf = 0; nf < 8; nf++){
            *(float2*)(base0 + nf*8) = make_float2(acc[fr][nf][0], acc[fr][nf][1]);
            *(float2*)(base1 + nf*8) = make_float2(acc[fr][nf][2], acc[fr][nf][3]);
        }
    }
}

// ==== kernel 4: fused {red1+ELU} -> gemm2 -> {W2T hi/lo + layer-2 tables} ====
__global__ void k_gemm2f(const float* __restrict__ Wo, const float* __restrict__ ao){
    __shared__ float As[32][65];
    __shared__ float Bs[64][40];
    __shared__ float Tw[40][33];
    __shared__ float invS[8][32];
    int tid = threadIdx.x;
    int row = tid & 31, cg = tid >> 5;
    int i0 = blockIdx.x*32;
    {
        int hh = tid>>5, rr = tid&31;
        float dsum = g_pd1[hh*NN + i0 + rr] + g_pd1[NH*NN + hh*NN + i0 + rr];
        invS[hh][rr] = 1.0f / dsum;
    }
    float acc[5] = {};
    for (int k0 = 0; k0 < FF; k0 += 64){
        __syncthreads();
        int hh = k0>>6;
        #pragma unroll
        for (int t = 0; t < 8; t++){
            int idx = tid + t*256;
            int rr = idx>>6, c = idx&63;
            float a = g_p1[(size_t)(i0+rr)*FF + k0 + c]
                    + g_p1[(size_t)NN*FF + (size_t)(i0+rr)*FF + k0 + c];
            As[rr][c] = elu1(a * invS[hh][rr]);
        }
        for (int idx = tid; idx < 64*NC; idx += 256){
            int rr = idx/NC, c = idx - rr*NC;
            Bs[rr][c] = Wo[(size_t)(k0+rr)*NC + c];
        }
        __syncthreads();
        #pragma unroll 8
        for (int kk = 0; kk < 64; kk++){
            float a = As[row][kk];
            #pragma unroll
            for (int q = 0; q < 5; q++) acc[q] += a * Bs[kk][cg*5+q];
        }
    }
    #pragma unroll
    for (int q = 0; q < 5; q++) Tw[cg*5+q][row] = acc[q];
    __syncthreads();
    for (int e = tid; e < NC*32; e += 256){
        int d = e>>5, il = e&31;
        float v = Tw[d][il];
        __nv_bfloat16 hb = __float2bfloat16(v);
        __nv_bfloat16 lb = __float2bfloat16(v - __bfloat162float(hb));
        g_W2T_hi[(size_t)d*NN + i0 + il] = hb;
        g_W2T_lo[(size_t)d*NN + i0 + il] = lb;
    }
    if (tid < 32){
        float p1 = 0.f, p2 = 0.f;
        #pragma unroll 8
        for (int d = 0; d < NC; d++){
            float v = Tw[d][tid];
            p1 += v*ao[d]; p2 += v*ao[NC+d];
        }
        g_t1b[i0+tid] = make_float4(expf(p1), expf(LRA*p1), p1, 0.f);
        g_t2b[i0+tid] = make_float4(expf(p2), expf(LRA*p2), p2, 0.f);
    }
}

// === kernel 6: layer-2 attention, HMMA hi/lo, j-split x4 ===
__global__ void __launch_bounds__(256) k_att2_mma(){
    __shared__ float4 s_tbl[128];
    __shared__ uint4 s_adj[128];
    __shared__ uint2 Wf_hi[40][32];
    __shared__ uint2 Wf_lo[40][32];

    int tid = threadIdx.x, wid = tid>>5, lane = tid&31;
    int i0 = blockIdx.x*128, js = blockIdx.y;
    int tig = lane & 3;
    int r0l = wid*16 + (lane>>2);
    int r1l = r0l + 8;

    float4 t1a = g_t1b[i0 + r0l];
    float4 t1b = g_t1b[i0 + r1l];
    float e1p0=t1a.x, e1n0=t1a.y, f10=t1a.z;
    float e1p1=t1b.x, e1n1=t1b.y, f11=t1b.z;
    float ds0 = 0.f, ds1 = 0.f;

    float acc[5][4];
    #pragma unroll
    for (int nf = 0; nf < 5; nf++){ acc[nf][0]=acc[nf][1]=acc[nf][2]=acc[nf][3]=0.f; }

    #pragma unroll 1
    for (int t = js*8; t < js*8 + 8; t++){
        int j0 = t*128;
        __syncthreads();
        if (tid < 128){
            s_tbl[tid] = g_t2b[j0 + tid];
            s_adj[tid] = *(const uint4*)(g_adjbit2 + (size_t)(i0+tid)*128 + t*4);
        }
        #pragma unroll
        for (int q = 0; q < 5; q++){
            int e = q*256 + tid;
            int fh = e>>5, ln = e&31;
            int nf = fh>>3, c = fh&7;
            int d = nf*8 + (ln>>2);
            int jj = c*16 + (ln&3)*2;
            size_t src = (size_t)d*NN + j0 + jj;
            Wf_hi[fh][ln] = make_uint2(*(const uint32_t*)(g_W2T_hi + src),
                                       *(const uint32_t*)(g_W2T_hi + src + 8));
            Wf_lo[fh][ln] = make_uint2(*(const uint32_t*)(g_W2T_lo + src),
                                       *(const uint32_t*)(g_W2T_lo + src + 8));
        }
        __syncthreads();

        #pragma unroll 2
        for (int c = 0; c < 8; c++){
            int p0 = c*16 + tig*2;
            float4 ta = s_tbl[p0], tb = s_tbl[p0+1], tc = s_tbl[p0+8], td = s_tbl[p0+9];
            uint32_t w0 = ((const uint32_t*)&s_adj[r0l])[c>>1] >> ((c&1)*16);
            uint32_t w1 = ((const uint32_t*)&s_adj[r1l])[c>>1] >> ((c&1)*16);
            int b0 = tig*2, b1 = b0+1, b2 = b0+8, b3 = b0+9;

            float v00,v01,v02,v03, v10,v11,v12,v13;
            PV(ta,e1p0,e1n0,f10,w0,b0,v00); PV(tb,e1p0,e1n0,f10,w0,b1,v01);
            PV(tc,e1p0,e1n0,f10,w0,b2,v02); PV(td,e1p0,e1n0,f10,w0,b3,v03);
            PV(ta,e1p1,e1n1,f11,w1,b0,v10); PV(tb,e1p1,e1n1,f11,w1,b1,v11);
            PV(tc,e1p1,e1n1,f11,w1,b2,v12); PV(td,e1p1,e1n1,f11,w1,b3,v13);
            ds0 += (v00+v01)+(v02+v03);
            ds1 += (v10+v11)+(v12+v13);

            uint32_t ah[4], al[4];
            ah[0] = bf2pack(v00, v01); ah[1] = bf2pack(v10, v11);
            ah[2] = bf2pack(v02, v03); ah[3] = bf2pack(v12, v13);
            al[0] = bf2pack(v00 - bflow(ah[0]), v01 - bfhigh(ah[0]));
            al[1] = bf2pack(v10 - bflow(ah[1]), v11 - bfhigh(ah[1]));
            al[2] = bf2pack(v02 - bflow(ah[2]), v03 - bfhigh(ah[2]));
            al[3] = bf2pack(v12 - bflow(ah[3]), v13 - bfhigh(ah[3]));

            #pragma unroll
            for (int nf = 0; nf < 5; nf++){
                uint2 bh = Wf_hi[nf*8+c][lane];
                uint2 bl = Wf_lo[nf*8+c][lane];
                mma_bf16(acc[nf], ah, bh.x, bh.y);
                mma_bf16(acc[nf], ah, bl.x, bl.y);
                mma_bf16(acc[nf], al, bh.x, bh.y);
            }
        }
    }

    ds0 += __shfl_xor_sync(0xffffffffu, ds0, 1);
    ds0 += __shfl_xor_sync(0xffffffffu, ds0, 2);
    ds1 += __shfl_xor_sync(0xffffffffu, ds1, 1);
    ds1 += __shfl_xor_sync(0xffffffffu, ds1, 2);
    if (tig == 0){
        g_pd2[js*NN + i0 + r0l] = ds0;
        g_pd2[js*NN + i0 + r1l] = ds1;
    }

    float* Pb = g_p2 + (size_t)js*NN*NC;
    float* base0 = &Pb[(size_t)(i0+r0l)*NC + tig*2];
    float* base1 = &Pb[(size_t)(i0+r1l)*NC + tig*2];
    #pragma unroll
    for (int nf = 0; nf < 5; nf++){
        *(float2*)(base0 + nf*8) = make_float2(acc[nf][0], acc[nf][1]);
        *(float2*)(base1 + nf*8) = make_float2(acc[nf][2], acc[nf][3]);
    }
}

// ====== kernel 7: fused merge + ELU + log_softmax (one warp per row) ======
__global__ void k_final(float* __restrict__ out){
    int w = threadIdx.x>>5, lane = threadIdx.x & 31;
    int i = blockIdx.x*8 + w;
    float dsum = g_pd2[i] + g_pd2[NN+i] + g_pd2[2*NN+i] + g_pd2[3*NN+i];
    float inv = 1.0f / dsum;
    size_t b = (size_t)i*NC;
    float v0 = elu1((g_p2[b+lane] + g_p2[(size_t)NN*NC + b + lane]
                   + g_p2[(size_t)2*NN*NC + b + lane] + g_p2[(size_t)3*NN*NC + b + lane]) * inv);
    float v1 = -1e30f;
    if (lane < 8){
        size_t c = b + 32 + lane;
        v1 = elu1((g_p2[c] + g_p2[(size_t)NN*NC + c]
                 + g_p2[(size_t)2*NN*NC + c] + g_p2[(size_t)3*NN*NC + c]) * inv);
    }
    float m = fmaxf(v0, v1);
    #pragma unroll
    for (int o = 16; o; o >>= 1) m = fmaxf(m, __shfl_xor_sync(0xffffffffu, m, o));
    float s = expf(v0 - m) + ((lane < 8) ? expf(v1 - m) : 0.f);
    #pragma unroll
    for (int o = 16; o; o >>= 1) s += __shfl_xor_sync(0xffffffffu, s, o);
    float ls = m + logf(s);
    out[b + lane] = v0 - ls;
    if (lane < 8) out[b + 32 + lane] = v1 - ls;
}

// ============================== launch ==============================
extern "C" void kernel_launch(void* const* d_in, const int* in_sizes, int n_in,
                              void* d_out, int out_size){
    const float* x  = (const float*)d_in[0];
    const int*   adj= (const int*)  d_in[1];
    const float* W1 = (const float*)d_in[2];
    const float* a1 = (const float*)d_in[3];
    const float* Wo = (const float*)d_in[4];
    const float* ao = (const float*)d_in[5];
    float* out = (float*)d_out;

    static int smem_set = 0;
    if (!smem_set){
        cudaFuncSetAttribute(k_gemm1h, cudaFuncAttributeMaxDynamicSharedMemorySize, 128*68*4);
        smem_set = 1;
    }

    k_pack   <<<dim3(2048, 2), 256>>>(adj);
    k_split  <<<1280, 256>>>(x, W1);
    k_gemm1h <<<dim3(32, 8), 256, 128*68*4>>>(a1);
    k_att1h  <<<dim3(8, 16, 2), 256>>>();
    k_gemm2f <<<128, 256>>>(Wo, ao);
    k_att2_mma<<<dim3(32, 4), 256>>>();
    k_final  <<<512, 256>>>(out);
}